// round 5
// baseline (speedup 1.0000x reference)
#include <cuda_runtime.h>
#include <cuda_fp16.h>
#include <cstdint>
#include <math.h>

#define Hdim 1024
#define Bq 64
#define Sq 512
#define NG 4096                 // 4*H
#define NROWS (Sq*Bq)           // 32768
#define HH (Hdim*Hdim)          // 1048576
#define NCTA 128
#define WH16OFF ((size_t)2*4*HH)

// ---------------- scratch (device globals; no allocations allowed) ----------------
__device__ __half g_W16[(size_t)4 * 4 * HH];        // Wi (2 layers) then Wh (2 layers), [l][g][k][n]
__device__ __half g_x16[(size_t)Bq * Sq * Hdim];    // x converted to half, [b][s][k]
__device__ __half g_gx16[(size_t)NROWS * NG];       // input-side gate pre-activations (+biases)
__device__ __half g_seq16[(size_t)Sq * Bq * Hdim];  // layer-0 hidden sequence [S][B][H]
__device__ __half g_h16[2][Bq * Hdim];              // recurrent h double buffer (half)
__device__ float g_h[2][Bq * Hdim];                 // final h per layer (fp32)
__device__ float g_c[2][Bq * Hdim];                 // final c per layer (fp32)
__device__ unsigned g_flag[NCTA];                   // monotonic per-CTA step flags

// ---------------- helpers ----------------
__device__ __forceinline__ uint32_t sptr(const void* p) {
    return (uint32_t)__cvta_generic_to_shared(p);
}

__device__ __forceinline__ void mma_f16(float* d, const uint32_t* a, const uint32_t* b) {
    asm volatile(
        "mma.sync.aligned.m16n8k16.row.col.f32.f16.f16.f32 "
        "{%0,%1,%2,%3}, {%4,%5,%6,%7}, {%8,%9}, {%0,%1,%2,%3};\n"
        : "+f"(d[0]), "+f"(d[1]), "+f"(d[2]), "+f"(d[3])
        : "r"(a[0]), "r"(a[1]), "r"(a[2]), "r"(a[3]), "r"(b[0]), "r"(b[1]));
}

__device__ __forceinline__ void ldm_x4(uint32_t* r, uint32_t addr) {
    asm volatile("ldmatrix.sync.aligned.m8n8.x4.shared.b16 {%0,%1,%2,%3}, [%4];"
        : "=r"(r[0]), "=r"(r[1]), "=r"(r[2]), "=r"(r[3]) : "r"(addr));
}
__device__ __forceinline__ void ldm_x4t(uint32_t* r, uint32_t addr) {
    asm volatile("ldmatrix.sync.aligned.m8n8.x4.trans.shared.b16 {%0,%1,%2,%3}, [%4];"
        : "=r"(r[0]), "=r"(r[1]), "=r"(r[2]), "=r"(r[3]) : "r"(addr));
}
__device__ __forceinline__ void ldm_x2t(uint32_t* r, uint32_t addr) {
    asm volatile("ldmatrix.sync.aligned.m8n8.x2.trans.shared.b16 {%0,%1}, [%2];"
        : "=r"(r[0]), "=r"(r[1]) : "r"(addr));
}

__device__ __forceinline__ void cp16(void* dst, const void* src) {
    uint32_t d = sptr(dst);
    asm volatile("cp.async.cg.shared.global [%0], [%1], 16;\n" :: "r"(d), "l"(src));
}
#define CP_COMMIT() asm volatile("cp.async.commit_group;\n")
#define CPW(n) asm volatile("cp.async.wait_group %0;\n" :: "n"(n))
__device__ __forceinline__ void cp_wait_n(int n) {
    switch (n) {
        case 0: CPW(0); break; case 1: CPW(1); break; case 2: CPW(2); break;
        case 3: CPW(3); break; case 4: CPW(4); break; case 5: CPW(5); break;
        case 6: CPW(6); break; default: CPW(7); break;
    }
}

// ---------------- prep: convert weights and x to half ----------------
__global__ void prep_kernel(const float* __restrict__ Wi, const float* __restrict__ Wh,
                            const float* __restrict__ x) {
    size_t i = (size_t)blockIdx.x * 256 + threadIdx.x;
    if (i < (size_t)2 * 4 * HH) {
        g_W16[i] = __float2half(Wi[i]);
        g_W16[WH16OFF + i] = __float2half(Wh[i]);
    }
    if (i < (size_t)Bq * Sq * Hdim) g_x16[i] = __float2half(x[i]);
}

// ---------------- projection GEMM: gx16 = X @ Wi[l] + (bi[l]+bh[l]) ----------------
// fp16 HMMA m16n8k16, CTA tile 128(M)x64(N), K chunks of 32, double-buffered.
// 8 warps as 4(M)x2(N), warp tile 32x32.
__global__ void __launch_bounds__(256, 3)
proj_kernel(int layer, const float* __restrict__ bi_all, const float* __restrict__ bh_all) {
    __shared__ __half As[2][128 * 40];   // pitch 40 halves = 80B (odd x16)
    __shared__ __half Bs[2][32 * 72];    // pitch 72 halves = 144B (odd x16)

    const int tid = threadIdx.x, lane = tid & 31, w = tid >> 5;
    const int g = lane >> 2, t4 = lane & 3;
    const int wm = w & 3, wn = w >> 2;
    const int rbase = blockIdx.y * 128;
    const int n0 = blockIdx.x * 64;
    const int gate = n0 >> 10, h0 = n0 & 1023;

    const __half* Wp = g_W16 + (size_t)layer * 4 * HH + (size_t)gate * HH + h0;
    const __half* Ap = (layer == 0) ? g_x16 : g_seq16;

    float acc[2][4][4];
#pragma unroll
    for (int a = 0; a < 2; a++)
#pragma unroll
        for (int b = 0; b < 4; b++)
#pragma unroll
            for (int c = 0; c < 4; c++) acc[a][b][c] = 0.f;

    auto loadA = [&](int buf, int kb) {
#pragma unroll
        for (int o = 0; o < 2; o++) {
            int idx = tid + o * 256;
            int r = idx >> 2, c = idx & 3;
            int grow = rbase + r;
            const __half* src;
            if (layer == 0) {
                int b = grow & 63, s = grow >> 6;
                src = Ap + ((size_t)b * Sq + s) * Hdim + kb + c * 8;
            } else {
                src = Ap + (size_t)grow * Hdim + kb + c * 8;
            }
            cp16(&As[buf][r * 40 + c * 8], src);
        }
    };
    auto loadB = [&](int buf, int kb) {
        int r = tid >> 3, c = tid & 7;
        cp16(&Bs[buf][r * 72 + c * 8], Wp + (size_t)(kb + r) * Hdim + c * 8);
    };

    loadA(0, 0); loadB(0, 0); CP_COMMIT();

    const int arow = lane & 15, aoff = (lane & 16) ? 8 : 0;
    const int NKC = Hdim / 32;  // 32
    for (int kc = 0; kc < NKC; kc++) {
        int cur = kc & 1;
        if (kc + 1 < NKC) {
            loadA(cur ^ 1, (kc + 1) * 32);
            loadB(cur ^ 1, (kc + 1) * 32);
            CP_COMMIT();
            CPW(1);
        } else {
            CPW(0);
        }
        __syncthreads();
        const __half* Ab = As[cur];
        const __half* Bb = Bs[cur];
#pragma unroll
        for (int ks2 = 0; ks2 < 2; ks2++) {
            uint32_t af[2][4], bf[2][4];
#pragma unroll
            for (int mt = 0; mt < 2; mt++)
                ldm_x4(af[mt], sptr(Ab + (wm * 32 + mt * 16 + arow) * 40 + ks2 * 16 + aoff));
#pragma unroll
            for (int nt = 0; nt < 2; nt++)
                ldm_x4t(bf[nt], sptr(Bb + (ks2 * 16 + arow) * 72 + wn * 32 + nt * 16 + aoff));
#pragma unroll
            for (int mt = 0; mt < 2; mt++)
#pragma unroll
                for (int q = 0; q < 4; q++)
                    mma_f16(acc[mt][q], af[mt], &bf[q >> 1][(q & 1) * 2]);
        }
        __syncthreads();
    }

    // epilogue: add (bi + bh), store half2
    const float* bi = bi_all + layer * NG;
    const float* bh = bh_all + layer * NG;
#pragma unroll
    for (int mt = 0; mt < 2; mt++) {
        int r0 = rbase + wm * 32 + mt * 16 + g;
#pragma unroll
        for (int q = 0; q < 4; q++) {
            int ng = n0 + wn * 32 + q * 8 + 2 * t4;
            float b0 = bi[ng] + bh[ng];
            float b1 = bi[ng + 1] + bh[ng + 1];
            *reinterpret_cast<__half2*>(g_gx16 + (size_t)r0 * NG + ng) =
                __floats2half2_rn(acc[mt][q][0] + b0, acc[mt][q][1] + b1);
            *reinterpret_cast<__half2*>(g_gx16 + (size_t)(r0 + 8) * NG + ng) =
                __floats2half2_rn(acc[mt][q][2] + b0, acc[mt][q][3] + b1);
        }
    }
}

// ---------------- persistent recurrent kernel: one launch per layer ----------------
// 128 CTAs x 512 threads. CTA owns h-cols [cta*8, cta*8+8) x 4 gates = 32 N cols.
// Wh slice (half) resident in SMEM (80KB); full h_t (132KB) staged per step.
// 16 warps as 4(M)x4(N), warp tile 16x8; 4 accumulation chains per thread.
__global__ void __launch_bounds__(512, 1)
recur_kernel(int layer) {
    extern __shared__ unsigned char smraw[];
    __half* Bs  = (__half*)smraw;                       // [1024][40]  Wh slice
    __half* As  = (__half*)(smraw + 81920);             // [64][1032]  full h staging
    float*  pre = (float*)(smraw + 81920 + 132096);     // [64][33]    pre-activations
    __half* gxs = (__half*)((char*)pre + 8448);         // [64][32]    gx staging
    float*  cs  = (float*)((char*)gxs + 4096);          // [512]       c-state

    const int tid = threadIdx.x, cta = blockIdx.x;
    const int lane = tid & 31, w = tid >> 5;
    const int g = lane >> 2, t4 = lane & 3;
    const int wm = w & 3, wn = w >> 2;     // warp grid 4(M) x 4(N), warp tile 16x8
    const int n0 = cta * 8;
    const int arow = lane & 15, aoff = (lane & 16) ? 8 : 0;

    unsigned F0 = *(volatile unsigned*)&g_flag[cta];   // own flag; all equal at entry

    // load Wh slice into SMEM: Bs[k][gate*8+j], half, k-major rows (one commit group)
    const __half* Whp = g_W16 + WH16OFF + (size_t)layer * 4 * HH;
    for (int i = tid; i < 4096; i += 512) {
        int k = i >> 2, gt = i & 3;
        cp16(&Bs[k * 40 + gt * 8], Whp + (size_t)gt * HH + (size_t)k * Hdim + n0);
    }
    CP_COMMIT();

    if (tid < 512) cs[tid] = 0.f;
    if (tid < 64)   // zero own slice of h buffer 0 (16B per row)
        *reinterpret_cast<uint4*>(&g_h16[0][tid * Hdim + n0]) = make_uint4(0, 0, 0, 0);
    __threadfence();
    __syncthreads();
    if (tid == 0) *(volatile unsigned*)&g_flag[cta] = F0 + 1;

    for (int t = 0; t < Sq; t++) {
        // wait: all CTAs produced h for step t (tight spin, no nanosleep)
        unsigned need = F0 + 1 + t;
        if (tid < NCTA) {
            volatile unsigned* f = &g_flag[tid];
            while ((int)(*f - need) < 0) {}
        }
        __syncthreads();

        const __half* curh = g_h16[t & 1];
        __half* nxth = g_h16[(t + 1) & 1];

        // gx staging (joins first commit group)
        if (tid < 256) {
            int r = tid >> 2, gt = tid & 3;
            cp16(&gxs[r * 32 + gt * 8],
                 g_gx16 + ((size_t)(t * 64 + r)) * NG + (size_t)gt * 1024 + n0);
        }
        // stage the whole h: 16 chunks of 64 k-cols, 8 commit groups of 2 chunks
#pragma unroll
        for (int kp = 0; kp < 8; kp++) {
#pragma unroll
            for (int kh = 0; kh < 2; kh++) {
                int kc = kp * 2 + kh;
                int r = tid >> 3, c = tid & 7;
                cp16(&As[r * 1032 + kc * 64 + c * 8],
                     curh + (size_t)r * Hdim + kc * 64 + c * 8);
            }
            CP_COMMIT();
        }

        float accE[4], accO[4];
#pragma unroll
        for (int a = 0; a < 4; a++) { accE[a] = 0.f; accO[a] = 0.f; }

#pragma unroll
        for (int kp = 0; kp < 8; kp++) {
            cp_wait_n(7 - kp);
            __syncthreads();
#pragma unroll
            for (int kh = 0; kh < 2; kh++) {
                int kc = kp * 2 + kh;
#pragma unroll
                for (int ks2 = 0; ks2 < 4; ks2++) {
                    uint32_t af[4], bf[2];
                    ldm_x4(af, sptr(As + (wm * 16 + arow) * 1032 + kc * 64 + ks2 * 16 + aoff));
                    ldm_x2t(bf, sptr(Bs + (kc * 64 + ks2 * 16 + arow) * 40 + wn * 8));
                    mma_f16((ks2 & 1) ? accO : accE, af, bf);
                }
            }
        }

        // stage pre-activations (sum the two chains)
        {
            int col = wn * 8 + 2 * t4;
            pre[(wm * 16 + g) * 33 + col]         = accE[0] + accO[0];
            pre[(wm * 16 + g) * 33 + col + 1]     = accE[1] + accO[1];
            pre[(wm * 16 + g + 8) * 33 + col]     = accE[2] + accO[2];
            pre[(wm * 16 + g + 8) * 33 + col + 1] = accE[3] + accO[3];
        }
        __syncthreads();

        // fused cell update (1 element per thread)
        {
            int p = tid;
            int b = p >> 3, j = p & 7;
            float v0 = pre[b * 33 + j]      + __half2float(gxs[b * 32 + j]);
            float v1 = pre[b * 33 + 8 + j]  + __half2float(gxs[b * 32 + 8 + j]);
            float v2 = pre[b * 33 + 16 + j] + __half2float(gxs[b * 32 + 16 + j]);
            float v3 = pre[b * 33 + 24 + j] + __half2float(gxs[b * 32 + 24 + j]);
            float i_ = 1.f / (1.f + expf(-v0));
            float f_ = 1.f / (1.f + expf(-v1));
            float gg = tanhf(v2);
            float o_ = 1.f / (1.f + expf(-v3));
            float cn = f_ * cs[p] + i_ * gg;
            float hn = o_ * tanhf(cn);
            cs[p] = cn;
            __half hr = __float2half(hn);
            nxth[b * Hdim + n0 + j] = hr;
            if (layer == 0) g_seq16[((size_t)t * 64 + b) * Hdim + n0 + j] = hr;
            if (t == Sq - 1) {
                g_h[layer][b * Hdim + n0 + j] = hn;
                g_c[layer][b * Hdim + n0 + j] = cn;
            }
        }
        __threadfence();
        __syncthreads();
        if (tid == 0) *(volatile unsigned*)&g_flag[cta] = F0 + 2 + t;
    }
}

// ---------------- dummy: aligns launch index so ncu (-s 5) profiles recur ----------------
__global__ void dummy_kernel() {}

// ---------------- finalize: pack output tuple (seq_last, h_n[2], c_n[2]) ----------------
__global__ void finalize_kernel(float* __restrict__ out, int out_size) {
    int idx = blockIdx.x * 256 + threadIdx.x;  // 0..65535
    const int N1 = Bq * Hdim;
    if (idx + 0 * N1 < out_size) out[idx]          = g_h[1][idx];  // seq[:, -1, :]
    if (idx + 1 * N1 < out_size) out[idx + N1]     = g_h[0][idx];  // h_n layer 0
    if (idx + 2 * N1 < out_size) out[idx + 2 * N1] = g_h[1][idx];  // h_n layer 1
    if (idx + 3 * N1 < out_size) out[idx + 3 * N1] = g_c[0][idx];  // c_n layer 0
    if (idx + 4 * N1 < out_size) out[idx + 4 * N1] = g_c[1][idx];  // c_n layer 1
}

// ---------------- launch: 7 graph nodes total ----------------
extern "C" void kernel_launch(void* const* d_in, const int* in_sizes, int n_in,
                              void* d_out, int out_size) {
    const float* x  = (const float*)d_in[0];
    const float* Wi = (const float*)d_in[1];
    const float* bi = (const float*)d_in[2];
    const float* Wh = (const float*)d_in[3];
    const float* bh = (const float*)d_in[4];
    float* out = (float*)d_out;
    (void)in_sizes; (void)n_in;

    const int recur_smem = 81920 + 132096 + 8448 + 4096 + 2048;  // 228608 B
    cudaFuncSetAttribute(recur_kernel, cudaFuncAttributeMaxDynamicSharedMemorySize,
                         recur_smem);

    prep_kernel<<<131072, 256>>>(Wi, Wh, x);            // launch 0
    proj_kernel<<<dim3(NG / 64, NROWS / 128), 256>>>(0, bi, bh);   // 1
    recur_kernel<<<NCTA, 512, recur_smem>>>(0);          // 2
    proj_kernel<<<dim3(NG / 64, NROWS / 128), 256>>>(1, bi, bh);   // 3
    dummy_kernel<<<1, 32>>>();                           // 4
    recur_kernel<<<NCTA, 512, recur_smem>>>(1);          // 5  <- ncu -s 5 -c 1 lands here
    finalize_kernel<<<256, 256>>>(out, out_size);        // 6
}

// round 6
// speedup vs baseline: 1.4056x; 1.4056x over previous
#include <cuda_runtime.h>
#include <cuda_fp16.h>
#include <cstdint>
#include <math.h>

#define Hdim 1024
#define Bq 64
#define Sq 512
#define NG 4096                 // 4*H
#define NROWS (Sq*Bq)           // 32768
#define HH (Hdim*Hdim)          // 1048576
#define NCTA 128
#define WH16OFF ((size_t)2*4*HH)

// ---------------- scratch (device globals; no allocations allowed) ----------------
__device__ __half g_W16[(size_t)4 * 4 * HH];        // Wi (2 layers) then Wh (2 layers), [l][g][k][n]
__device__ __half g_x16[(size_t)Bq * Sq * Hdim];    // x converted to half, [b][s][k]
__device__ __half g_gx16[(size_t)NROWS * NG];       // input-side gate pre-activations (+biases)
__device__ __half g_seq16[(size_t)Sq * Bq * Hdim];  // layer-0 hidden sequence [S][B][H]
__device__ __half g_h16[2][Bq * Hdim];              // recurrent h double buffer (half)
__device__ float g_h[2][Bq * Hdim];                 // final h per layer (fp32)
__device__ float g_c[2][Bq * Hdim];                 // final c per layer (fp32)
__device__ unsigned g_flag[NCTA * 8];               // per-CTA step flags, padded to 32B each
__device__ unsigned g_gen;                          // aggregated generation (published by CTA 0)

// ---------------- helpers ----------------
__device__ __forceinline__ uint32_t sptr(const void* p) {
    return (uint32_t)__cvta_generic_to_shared(p);
}

__device__ __forceinline__ void mma_f16(float* d, const uint32_t* a, const uint32_t* b) {
    asm volatile(
        "mma.sync.aligned.m16n8k16.row.col.f32.f16.f16.f32 "
        "{%0,%1,%2,%3}, {%4,%5,%6,%7}, {%8,%9}, {%0,%1,%2,%3};\n"
        : "+f"(d[0]), "+f"(d[1]), "+f"(d[2]), "+f"(d[3])
        : "r"(a[0]), "r"(a[1]), "r"(a[2]), "r"(a[3]), "r"(b[0]), "r"(b[1]));
}

__device__ __forceinline__ void ldm_x4(uint32_t* r, uint32_t addr) {
    asm volatile("ldmatrix.sync.aligned.m8n8.x4.shared.b16 {%0,%1,%2,%3}, [%4];"
        : "=r"(r[0]), "=r"(r[1]), "=r"(r[2]), "=r"(r[3]) : "r"(addr));
}
__device__ __forceinline__ void ldm_x4t(uint32_t* r, uint32_t addr) {
    asm volatile("ldmatrix.sync.aligned.m8n8.x4.trans.shared.b16 {%0,%1,%2,%3}, [%4];"
        : "=r"(r[0]), "=r"(r[1]), "=r"(r[2]), "=r"(r[3]) : "r"(addr));
}
__device__ __forceinline__ void ldm_x2t(uint32_t* r, uint32_t addr) {
    asm volatile("ldmatrix.sync.aligned.m8n8.x2.trans.shared.b16 {%0,%1}, [%2];"
        : "=r"(r[0]), "=r"(r[1]) : "r"(addr));
}

__device__ __forceinline__ void cp16(void* dst, const void* src) {
    uint32_t d = sptr(dst);
    asm volatile("cp.async.cg.shared.global [%0], [%1], 16;\n" :: "r"(d), "l"(src));
}
#define CP_COMMIT() asm volatile("cp.async.commit_group;\n")
#define CPW(n) asm volatile("cp.async.wait_group %0;\n" :: "n"(n))
__device__ __forceinline__ void cp_wait_n(int n) {
    switch (n) {
        case 0: CPW(0); break; case 1: CPW(1); break; case 2: CPW(2); break;
        case 3: CPW(3); break; case 4: CPW(4); break; case 5: CPW(5); break;
        case 6: CPW(6); break; default: CPW(7); break;
    }
}

// ---------------- prep: convert weights and x to half ----------------
__global__ void prep_kernel(const float* __restrict__ Wi, const float* __restrict__ Wh,
                            const float* __restrict__ x) {
    size_t i = (size_t)blockIdx.x * 256 + threadIdx.x;
    if (i < (size_t)2 * 4 * HH) {
        g_W16[i] = __float2half(Wi[i]);
        g_W16[WH16OFF + i] = __float2half(Wh[i]);
    }
    if (i < (size_t)Bq * Sq * Hdim) g_x16[i] = __float2half(x[i]);
}

// ---------------- projection GEMM: gx16 = X @ Wi[l] + (bi[l]+bh[l]) ----------------
// fp16 HMMA m16n8k16, CTA tile 128(M)x64(N), K chunks of 32, double-buffered.
// 8 warps as 4(M)x2(N), warp tile 32x32.
__global__ void __launch_bounds__(256, 3)
proj_kernel(int layer, const float* __restrict__ bi_all, const float* __restrict__ bh_all) {
    __shared__ __half As[2][128 * 40];   // pitch 40 halves = 80B (odd x16)
    __shared__ __half Bs[2][32 * 72];    // pitch 72 halves = 144B (odd x16)

    const int tid = threadIdx.x, lane = tid & 31, w = tid >> 5;
    const int g = lane >> 2, t4 = lane & 3;
    const int wm = w & 3, wn = w >> 2;
    const int rbase = blockIdx.y * 128;
    const int n0 = blockIdx.x * 64;
    const int gate = n0 >> 10, h0 = n0 & 1023;

    const __half* Wp = g_W16 + (size_t)layer * 4 * HH + (size_t)gate * HH + h0;
    const __half* Ap = (layer == 0) ? g_x16 : g_seq16;

    float acc[2][4][4];
#pragma unroll
    for (int a = 0; a < 2; a++)
#pragma unroll
        for (int b = 0; b < 4; b++)
#pragma unroll
            for (int c = 0; c < 4; c++) acc[a][b][c] = 0.f;

    auto loadA = [&](int buf, int kb) {
#pragma unroll
        for (int o = 0; o < 2; o++) {
            int idx = tid + o * 256;
            int r = idx >> 2, c = idx & 3;
            int grow = rbase + r;
            const __half* src;
            if (layer == 0) {
                int b = grow & 63, s = grow >> 6;
                src = Ap + ((size_t)b * Sq + s) * Hdim + kb + c * 8;
            } else {
                src = Ap + (size_t)grow * Hdim + kb + c * 8;
            }
            cp16(&As[buf][r * 40 + c * 8], src);
        }
    };
    auto loadB = [&](int buf, int kb) {
        int r = tid >> 3, c = tid & 7;
        cp16(&Bs[buf][r * 72 + c * 8], Wp + (size_t)(kb + r) * Hdim + c * 8);
    };

    loadA(0, 0); loadB(0, 0); CP_COMMIT();

    const int arow = lane & 15, aoff = (lane & 16) ? 8 : 0;
    const int NKC = Hdim / 32;  // 32
    for (int kc = 0; kc < NKC; kc++) {
        int cur = kc & 1;
        if (kc + 1 < NKC) {
            loadA(cur ^ 1, (kc + 1) * 32);
            loadB(cur ^ 1, (kc + 1) * 32);
            CP_COMMIT();
            CPW(1);
        } else {
            CPW(0);
        }
        __syncthreads();
        const __half* Ab = As[cur];
        const __half* Bb = Bs[cur];
#pragma unroll
        for (int ks2 = 0; ks2 < 2; ks2++) {
            uint32_t af[2][4], bf[2][4];
#pragma unroll
            for (int mt = 0; mt < 2; mt++)
                ldm_x4(af[mt], sptr(Ab + (wm * 32 + mt * 16 + arow) * 40 + ks2 * 16 + aoff));
#pragma unroll
            for (int nt = 0; nt < 2; nt++)
                ldm_x4t(bf[nt], sptr(Bb + (ks2 * 16 + arow) * 72 + wn * 32 + nt * 16 + aoff));
#pragma unroll
            for (int mt = 0; mt < 2; mt++)
#pragma unroll
                for (int q = 0; q < 4; q++)
                    mma_f16(acc[mt][q], af[mt], &bf[q >> 1][(q & 1) * 2]);
        }
        __syncthreads();
    }

    // epilogue: add (bi + bh), store half2
    const float* bi = bi_all + layer * NG;
    const float* bh = bh_all + layer * NG;
#pragma unroll
    for (int mt = 0; mt < 2; mt++) {
        int r0 = rbase + wm * 32 + mt * 16 + g;
#pragma unroll
        for (int q = 0; q < 4; q++) {
            int ng = n0 + wn * 32 + q * 8 + 2 * t4;
            float b0 = bi[ng] + bh[ng];
            float b1 = bi[ng + 1] + bh[ng + 1];
            *reinterpret_cast<__half2*>(g_gx16 + (size_t)r0 * NG + ng) =
                __floats2half2_rn(acc[mt][q][0] + b0, acc[mt][q][1] + b1);
            *reinterpret_cast<__half2*>(g_gx16 + (size_t)(r0 + 8) * NG + ng) =
                __floats2half2_rn(acc[mt][q][2] + b0, acc[mt][q][3] + b1);
        }
    }
}

// ---------------- persistent recurrent kernel: one launch per layer ----------------
// 128 CTAs x 512 threads. CTA owns h-cols [cta*8, cta*8+8) x 4 gates = 32 N cols.
// Wh slice (half) resident in SMEM (80KB); full h_t (132KB) staged per step.
// Relay barrier: producers write padded flags; CTA0 aggregates and publishes g_gen;
// consumers poll the single g_gen word.
__global__ void __launch_bounds__(512, 1)
recur_kernel(int layer) {
    extern __shared__ unsigned char smraw[];
    __half* Bs  = (__half*)smraw;                       // [1024][40]  Wh slice
    __half* As  = (__half*)(smraw + 81920);             // [64][1032]  full h staging
    float*  pre = (float*)(smraw + 81920 + 132096);     // [64][33]    pre-activations
    __half* gxs = (__half*)((char*)pre + 8448);         // [64][32]    gx staging
    float*  cs  = (float*)((char*)gxs + 4096);          // [512]       c-state

    const int tid = threadIdx.x, cta = blockIdx.x;
    const int lane = tid & 31, w = tid >> 5;
    const int g = lane >> 2, t4 = lane & 3;
    const int wm = w & 3, wn = w >> 2;     // warp grid 4(M) x 4(N), warp tile 16x8
    const int n0 = cta * 8;
    const int arow = lane & 15, aoff = (lane & 16) ? 8 : 0;

    unsigned F0 = *(volatile unsigned*)&g_flag[cta * 8];   // all flags equal at entry

    // load Wh slice into SMEM: Bs[k][gate*8+j], half, k-major rows (one commit group)
    const __half* Whp = g_W16 + WH16OFF + (size_t)layer * 4 * HH;
    for (int i = tid; i < 4096; i += 512) {
        int k = i >> 2, gt = i & 3;
        cp16(&Bs[k * 40 + gt * 8], Whp + (size_t)gt * HH + (size_t)k * Hdim + n0);
    }
    CP_COMMIT();

    cs[tid] = 0.f;
    if (tid < 64)   // zero own slice of h buffer 0 (16B per row)
        *reinterpret_cast<uint4*>(&g_h16[0][tid * Hdim + n0]) = make_uint4(0, 0, 0, 0);
    __threadfence();
    __syncthreads();
    if (tid == 0) *(volatile unsigned*)&g_flag[cta * 8] = F0 + 1;

    for (int t = 0; t < Sq; t++) {
        const unsigned need = F0 + 1 + t;

        // gx prefetch (independent of h) BEFORE the rendezvous; own commit group
        if (tid < 256) {
            int r = tid >> 2, gt = tid & 3;
            cp16(&gxs[r * 32 + gt * 8],
                 g_gx16 + ((size_t)(t * 64 + r)) * NG + (size_t)gt * 1024 + n0);
        }
        CP_COMMIT();

        // rendezvous
        if (cta == 0) {
            if (tid < NCTA) {
                volatile unsigned* f = &g_flag[tid * 8];
                while ((int)(*f - need) < 0) {}
            }
            __syncthreads();
            if (tid == 0) {
                __threadfence();
                *(volatile unsigned*)&g_gen = need;
            }
        } else {
            if (tid == 0) {
                volatile unsigned* gp = &g_gen;
                while ((int)(*gp - need) < 0) {}
            }
            __syncthreads();
        }

        const __half* curh = g_h16[t & 1];
        __half* nxth = g_h16[(t + 1) & 1];

        // stage the whole h: 16 chunks of 64 k-cols, 8 commit groups of 2 chunks
#pragma unroll
        for (int kp = 0; kp < 8; kp++) {
#pragma unroll
            for (int kh = 0; kh < 2; kh++) {
                int kc = kp * 2 + kh;
                int r = tid >> 3, c = tid & 7;
                cp16(&As[r * 1032 + kc * 64 + c * 8],
                     curh + (size_t)r * Hdim + kc * 64 + c * 8);
            }
            CP_COMMIT();
        }

        float accE[4], accO[4];
#pragma unroll
        for (int a = 0; a < 4; a++) { accE[a] = 0.f; accO[a] = 0.f; }

#pragma unroll
        for (int kp = 0; kp < 8; kp++) {
            cp_wait_n(7 - kp);     // drains gx group + pairs 0..kp (in-order groups)
            __syncthreads();
#pragma unroll
            for (int kh = 0; kh < 2; kh++) {
                int kc = kp * 2 + kh;
#pragma unroll
                for (int ks2 = 0; ks2 < 4; ks2++) {
                    uint32_t af[4], bf[2];
                    ldm_x4(af, sptr(As + (wm * 16 + arow) * 1032 + kc * 64 + ks2 * 16 + aoff));
                    ldm_x2t(bf, sptr(Bs + (kc * 64 + ks2 * 16 + arow) * 40 + wn * 8));
                    mma_f16((ks2 & 1) ? accO : accE, af, bf);
                }
            }
        }

        // stage pre-activations (sum the two chains)
        {
            int col = wn * 8 + 2 * t4;
            pre[(wm * 16 + g) * 33 + col]         = accE[0] + accO[0];
            pre[(wm * 16 + g) * 33 + col + 1]     = accE[1] + accO[1];
            pre[(wm * 16 + g + 8) * 33 + col]     = accE[2] + accO[2];
            pre[(wm * 16 + g + 8) * 33 + col + 1] = accE[3] + accO[3];
        }
        __syncthreads();

        // fused cell update (1 element per thread)
        {
            int p = tid;
            int b = p >> 3, j = p & 7;
            float v0 = pre[b * 33 + j]      + __half2float(gxs[b * 32 + j]);
            float v1 = pre[b * 33 + 8 + j]  + __half2float(gxs[b * 32 + 8 + j]);
            float v2 = pre[b * 33 + 16 + j] + __half2float(gxs[b * 32 + 16 + j]);
            float v3 = pre[b * 33 + 24 + j] + __half2float(gxs[b * 32 + 24 + j]);
            float i_ = 1.f / (1.f + expf(-v0));
            float f_ = 1.f / (1.f + expf(-v1));
            float gg = tanhf(v2);
            float o_ = 1.f / (1.f + expf(-v3));
            float cn = f_ * cs[p] + i_ * gg;
            float hn = o_ * tanhf(cn);
            cs[p] = cn;
            __half hr = __float2half(hn);
            nxth[b * Hdim + n0 + j] = hr;
            if (layer == 0) g_seq16[((size_t)t * 64 + b) * Hdim + n0 + j] = hr;
            if (t == Sq - 1) {
                g_h[layer][b * Hdim + n0 + j] = hn;
                g_c[layer][b * Hdim + n0 + j] = cn;
            }
        }
        __threadfence();
        __syncthreads();
        if (tid == 0) *(volatile unsigned*)&g_flag[cta * 8] = F0 + 2 + t;
    }
}

// ---------------- finalize: pack output tuple (seq_last, h_n[2], c_n[2]) ----------------
__global__ void finalize_kernel(float* __restrict__ out, int out_size) {
    int idx = blockIdx.x * 256 + threadIdx.x;  // 0..65535
    const int N1 = Bq * Hdim;
    if (idx + 0 * N1 < out_size) out[idx]          = g_h[1][idx];  // seq[:, -1, :]
    if (idx + 1 * N1 < out_size) out[idx + N1]     = g_h[0][idx];  // h_n layer 0
    if (idx + 2 * N1 < out_size) out[idx + 2 * N1] = g_h[1][idx];  // h_n layer 1
    if (idx + 3 * N1 < out_size) out[idx + 3 * N1] = g_c[0][idx];  // c_n layer 0
    if (idx + 4 * N1 < out_size) out[idx + 4 * N1] = g_c[1][idx];  // c_n layer 1
}

// ---------------- launch: 6 graph nodes total ----------------
extern "C" void kernel_launch(void* const* d_in, const int* in_sizes, int n_in,
                              void* d_out, int out_size) {
    const float* x  = (const float*)d_in[0];
    const float* Wi = (const float*)d_in[1];
    const float* bi = (const float*)d_in[2];
    const float* Wh = (const float*)d_in[3];
    const float* bh = (const float*)d_in[4];
    float* out = (float*)d_out;
    (void)in_sizes; (void)n_in;

    const int recur_smem = 81920 + 132096 + 8448 + 4096 + 2048;  // 228608 B
    cudaFuncSetAttribute(recur_kernel, cudaFuncAttributeMaxDynamicSharedMemorySize,
                         recur_smem);

    prep_kernel<<<131072, 256>>>(Wi, Wh, x);
    for (int l = 0; l < 2; l++) {
        proj_kernel<<<dim3(NG / 64, NROWS / 128), 256>>>(l, bi, bh);
        recur_kernel<<<NCTA, 512, recur_smem>>>(l);
    }
    finalize_kernel<<<256, 256>>>(out, out_size);
}

// round 7
// speedup vs baseline: 1.4063x; 1.0004x over previous
#include <cuda_runtime.h>
#include <cuda_fp16.h>
#include <cstdint>
#include <math.h>

#define Hdim 1024
#define Bq 64
#define Sq 512
#define NG 4096                 // 4*H
#define NROWS (Sq*Bq)           // 32768
#define HH (Hdim*Hdim)          // 1048576
#define NCTA 128
#define WH16OFF ((size_t)2*4*HH)

// ---------------- scratch (device globals; no allocations allowed) ----------------
__device__ __half g_W16[(size_t)4 * 4 * HH];        // Wi (2 layers) then Wh (2 layers), [l][g][k][n]
__device__ __half g_x16[(size_t)Bq * Sq * Hdim];    // x converted to half, [b][s][k]
__device__ __half g_gx16[(size_t)NROWS * NG];       // input-side gate pre-activations (+biases)
__device__ __half g_seq16[(size_t)Sq * Bq * Hdim];  // layer-0 hidden sequence [S][B][H]
__device__ __half g_h16[2][Bq * Hdim];              // recurrent h double buffer (half)
__device__ float g_h[2][Bq * Hdim];                 // final h per layer (fp32)
__device__ float g_c[2][Bq * Hdim];                 // final c per layer (fp32)
__device__ unsigned g_flag[NCTA * 8];               // per-CTA step flags, padded to 32B each
__device__ unsigned g_genv[8 * 8];                  // generation, 8 padded copies (32B apart)

// ---------------- helpers ----------------
__device__ __forceinline__ uint32_t sptr(const void* p) {
    return (uint32_t)__cvta_generic_to_shared(p);
}

__device__ __forceinline__ void mma_f16(float* d, const uint32_t* a, const uint32_t* b) {
    asm volatile(
        "mma.sync.aligned.m16n8k16.row.col.f32.f16.f16.f32 "
        "{%0,%1,%2,%3}, {%4,%5,%6,%7}, {%8,%9}, {%0,%1,%2,%3};\n"
        : "+f"(d[0]), "+f"(d[1]), "+f"(d[2]), "+f"(d[3])
        : "r"(a[0]), "r"(a[1]), "r"(a[2]), "r"(a[3]), "r"(b[0]), "r"(b[1]));
}

__device__ __forceinline__ void ldm_x4(uint32_t* r, uint32_t addr) {
    asm volatile("ldmatrix.sync.aligned.m8n8.x4.shared.b16 {%0,%1,%2,%3}, [%4];"
        : "=r"(r[0]), "=r"(r[1]), "=r"(r[2]), "=r"(r[3]) : "r"(addr));
}
__device__ __forceinline__ void ldm_x4t(uint32_t* r, uint32_t addr) {
    asm volatile("ldmatrix.sync.aligned.m8n8.x4.trans.shared.b16 {%0,%1,%2,%3}, [%4];"
        : "=r"(r[0]), "=r"(r[1]), "=r"(r[2]), "=r"(r[3]) : "r"(addr));
}

__device__ __forceinline__ void cp16(void* dst, const void* src) {
    uint32_t d = sptr(dst);
    asm volatile("cp.async.cg.shared.global [%0], [%1], 16;\n" :: "r"(d), "l"(src));
}
#define CP_COMMIT() asm volatile("cp.async.commit_group;\n")
#define CPW(n) asm volatile("cp.async.wait_group %0;\n" :: "n"(n))
__device__ __forceinline__ void cp_wait_n(int n) {
    switch (n) {
        case 0: CPW(0); break; case 1: CPW(1); break; case 2: CPW(2); break;
        case 3: CPW(3); break; case 4: CPW(4); break; case 5: CPW(5); break;
        case 6: CPW(6); break; default: CPW(7); break;
    }
}

// ---------------- prep: convert weights and x to half ----------------
__global__ void prep_kernel(const float* __restrict__ Wi, const float* __restrict__ Wh,
                            const float* __restrict__ x) {
    size_t i = (size_t)blockIdx.x * 256 + threadIdx.x;
    if (i < (size_t)2 * 4 * HH) {
        g_W16[i] = __float2half(Wi[i]);
        g_W16[WH16OFF + i] = __float2half(Wh[i]);
    }
    if (i < (size_t)Bq * Sq * Hdim) g_x16[i] = __float2half(x[i]);
}

// ---------------- projection GEMM: gx16 = X @ Wi[l] + (bi[l]+bh[l]) ----------------
// fp16 HMMA m16n8k16, CTA tile 128(M)x64(N), K chunks of 32, double-buffered,
// single __syncthreads per chunk. 8 warps as 4(M)x2(N), warp tile 32x32.
__global__ void __launch_bounds__(256, 3)
proj_kernel(int layer, const float* __restrict__ bi_all, const float* __restrict__ bh_all) {
    __shared__ __half As[2][128 * 40];   // pitch 40 halves = 80B
    __shared__ __half Bs[2][32 * 72];    // pitch 72 halves = 144B

    const int tid = threadIdx.x, lane = tid & 31, w = tid >> 5;
    const int g = lane >> 2, t4 = lane & 3;
    const int wm = w & 3, wn = w >> 2;
    const int rbase = blockIdx.y * 128;
    const int n0 = blockIdx.x * 64;
    const int gate = n0 >> 10, h0 = n0 & 1023;

    const __half* Wp = g_W16 + (size_t)layer * 4 * HH + (size_t)gate * HH + h0;
    const __half* Ap = (layer == 0) ? g_x16 : g_seq16;

    float acc[2][4][4];
#pragma unroll
    for (int a = 0; a < 2; a++)
#pragma unroll
        for (int b = 0; b < 4; b++)
#pragma unroll
            for (int c = 0; c < 4; c++) acc[a][b][c] = 0.f;

    auto loadA = [&](int buf, int kb) {
#pragma unroll
        for (int o = 0; o < 2; o++) {
            int idx = tid + o * 256;
            int r = idx >> 2, c = idx & 3;
            int grow = rbase + r;
            const __half* src;
            if (layer == 0) {
                int b = grow & 63, s = grow >> 6;
                src = Ap + ((size_t)b * Sq + s) * Hdim + kb + c * 8;
            } else {
                src = Ap + (size_t)grow * Hdim + kb + c * 8;
            }
            cp16(&As[buf][r * 40 + c * 8], src);
        }
    };
    auto loadB = [&](int buf, int kb) {
        int r = tid >> 3, c = tid & 7;
        cp16(&Bs[buf][r * 72 + c * 8], Wp + (size_t)(kb + r) * Hdim + c * 8);
    };

    loadA(0, 0); loadB(0, 0); CP_COMMIT();

    const int arow = lane & 15, aoff = (lane & 16) ? 8 : 0;
    const int NKC = Hdim / 32;  // 32
    for (int kc = 0; kc < NKC; kc++) {
        int cur = kc & 1;
        CPW(0);                 // only the group filling `cur` is in flight here
        __syncthreads();        // single barrier per chunk
        if (kc + 1 < NKC) {     // prefetch into the other buffer (no one reads it yet)
            loadA(cur ^ 1, (kc + 1) * 32);
            loadB(cur ^ 1, (kc + 1) * 32);
            CP_COMMIT();
        }
        const __half* Ab = As[cur];
        const __half* Bb = Bs[cur];
#pragma unroll
        for (int ks2 = 0; ks2 < 2; ks2++) {
            uint32_t af[2][4], bf[2][4];
#pragma unroll
            for (int mt = 0; mt < 2; mt++)
                ldm_x4(af[mt], sptr(Ab + (wm * 32 + mt * 16 + arow) * 40 + ks2 * 16 + aoff));
#pragma unroll
            for (int nt = 0; nt < 2; nt++)
                ldm_x4t(bf[nt], sptr(Bb + (ks2 * 16 + arow) * 72 + wn * 32 + nt * 16 + aoff));
#pragma unroll
            for (int mt = 0; mt < 2; mt++)
#pragma unroll
                for (int q = 0; q < 4; q++)
                    mma_f16(acc[mt][q], af[mt], &bf[q >> 1][(q & 1) * 2]);
        }
    }

    // epilogue: add (bi + bh), store half2
    const float* bi = bi_all + layer * NG;
    const float* bh = bh_all + layer * NG;
#pragma unroll
    for (int mt = 0; mt < 2; mt++) {
        int r0 = rbase + wm * 32 + mt * 16 + g;
#pragma unroll
        for (int q = 0; q < 4; q++) {
            int ng = n0 + wn * 32 + q * 8 + 2 * t4;
            float b0 = bi[ng] + bh[ng];
            float b1 = bi[ng + 1] + bh[ng + 1];
            *reinterpret_cast<__half2*>(g_gx16 + (size_t)r0 * NG + ng) =
                __floats2half2_rn(acc[mt][q][0] + b0, acc[mt][q][1] + b1);
            *reinterpret_cast<__half2*>(g_gx16 + (size_t)(r0 + 8) * NG + ng) =
                __floats2half2_rn(acc[mt][q][2] + b0, acc[mt][q][3] + b1);
        }
    }
}

// ---------------- persistent recurrent kernel: one launch per layer ----------------
// 128 CTAs x 512 threads. CTA owns h-cols [cta*8, cta*8+8) x 4 gates = 32 N cols.
// Relay barrier: producers write padded flags; CTA0 aggregates and publishes the
// generation to 8 padded copies; consumer CTA c polls copy c&7 (16 pollers/word).
__global__ void __launch_bounds__(512, 1)
recur_kernel(int layer) {
    extern __shared__ unsigned char smraw[];
    __half* Bs  = (__half*)smraw;                       // [1024][40]  Wh slice
    __half* As  = (__half*)(smraw + 81920);             // [64][1032]  full h staging
    float*  pre = (float*)(smraw + 81920 + 132096);     // [64][33]    pre-activations
    __half* gxs = (__half*)((char*)pre + 8448);         // [64][32]    gx staging
    float*  cs  = (float*)((char*)gxs + 4096);          // [512]       c-state

    const int tid = threadIdx.x, cta = blockIdx.x;
    const int lane = tid & 31, w = tid >> 5;
    const int g = lane >> 2, t4 = lane & 3;
    const int wm = w & 3, wn = w >> 2;     // warp grid 4(M) x 4(N), warp tile 16x8
    const int n0 = cta * 8;
    const int arow = lane & 15, aoff = (lane & 16) ? 8 : 0;

    unsigned F0 = *(volatile unsigned*)&g_flag[cta * 8];   // all flags equal at entry

    // load Wh slice into SMEM: Bs[k][gate*8+j], half, k-major rows (one commit group)
    const __half* Whp = g_W16 + WH16OFF + (size_t)layer * 4 * HH;
    for (int i = tid; i < 4096; i += 512) {
        int k = i >> 2, gt = i & 3;
        cp16(&Bs[k * 40 + gt * 8], Whp + (size_t)gt * HH + (size_t)k * Hdim + n0);
    }
    CP_COMMIT();

    cs[tid] = 0.f;
    if (tid < 64)   // zero own slice of h buffer 0 (16B per row)
        *reinterpret_cast<uint4*>(&g_h16[0][tid * Hdim + n0]) = make_uint4(0, 0, 0, 0);
    __threadfence();
    __syncthreads();
    if (tid == 0) *(volatile unsigned*)&g_flag[cta * 8] = F0 + 1;

    for (int t = 0; t < Sq; t++) {
        const unsigned need = F0 + 1 + t;

        // gx prefetch (independent of h) BEFORE the rendezvous; own commit group
        if (tid < 256) {
            int r = tid >> 2, gt = tid & 3;
            cp16(&gxs[r * 32 + gt * 8],
                 g_gx16 + ((size_t)(t * 64 + r)) * NG + (size_t)gt * 1024 + n0);
        }
        CP_COMMIT();

        // rendezvous (relay, replicated gen, nanosleep backoff)
        if (cta == 0) {
            if (tid < NCTA) {
                volatile unsigned* f = &g_flag[tid * 8];
                if ((int)(*f - need) < 0) {
                    do { __nanosleep(32); } while ((int)(*f - need) < 0);
                }
            }
            __syncthreads();
            if (tid < 8) {
                __threadfence();
                *(volatile unsigned*)&g_genv[tid * 8] = need;
            }
            __syncthreads();
        } else {
            if (tid == 0) {
                volatile unsigned* gp = &g_genv[(cta & 7) * 8];
                if ((int)(*gp - need) < 0) {
                    do { __nanosleep(32); } while ((int)(*gp - need) < 0);
                }
            }
            __syncthreads();
        }

        const __half* curh = g_h16[t & 1];
        __half* nxth = g_h16[(t + 1) & 1];

        // stage the whole h: 16 chunks of 64 k-cols, 8 commit groups of 2 chunks
#pragma unroll
        for (int kp = 0; kp < 8; kp++) {
#pragma unroll
            for (int kh = 0; kh < 2; kh++) {
                int kc = kp * 2 + kh;
                int r = tid >> 3, c = tid & 7;
                cp16(&As[r * 1032 + kc * 64 + c * 8],
                     curh + (size_t)r * Hdim + kc * 64 + c * 8);
            }
            CP_COMMIT();
        }

        float accE[4], accO[4];
#pragma unroll
        for (int a = 0; a < 4; a++) { accE[a] = 0.f; accO[a] = 0.f; }

#pragma unroll
        for (int kp = 0; kp < 8; kp++) {
            cp_wait_n(7 - kp);     // drains gx group + pairs 0..kp (in-order groups)
            __syncthreads();
#pragma unroll
            for (int ks4 = 0; ks4 < 4; ks4++) {   // 4 x k32 per chunk-pair
                int kb = kp * 128 + ks4 * 32;
                uint32_t afE[4], afO[4], bf[4];
                ldm_x4(afE, sptr(As + (wm * 16 + arow) * 1032 + kb + aoff));
                ldm_x4(afO, sptr(As + (wm * 16 + arow) * 1032 + kb + 16 + aoff));
                ldm_x4t(bf, sptr(Bs + (kb + lane) * 40 + wn * 8));
                mma_f16(accE, afE, bf);
                mma_f16(accO, afO, bf + 2);
            }
        }

        // stage pre-activations (sum the two chains)
        {
            int col = wn * 8 + 2 * t4;
            pre[(wm * 16 + g) * 33 + col]         = accE[0] + accO[0];
            pre[(wm * 16 + g) * 33 + col + 1]     = accE[1] + accO[1];
            pre[(wm * 16 + g + 8) * 33 + col]     = accE[2] + accO[2];
            pre[(wm * 16 + g + 8) * 33 + col + 1] = accE[3] + accO[3];
        }
        __syncthreads();

        // fused cell update (1 element per thread)
        {
            int p = tid;
            int b = p >> 3, j = p & 7;
            float v0 = pre[b * 33 + j]      + __half2float(gxs[b * 32 + j]);
            float v1 = pre[b * 33 + 8 + j]  + __half2float(gxs[b * 32 + 8 + j]);
            float v2 = pre[b * 33 + 16 + j] + __half2float(gxs[b * 32 + 16 + j]);
            float v3 = pre[b * 33 + 24 + j] + __half2float(gxs[b * 32 + 24 + j]);
            float i_ = 1.f / (1.f + expf(-v0));
            float f_ = 1.f / (1.f + expf(-v1));
            float gg = tanhf(v2);
            float o_ = 1.f / (1.f + expf(-v3));
            float cn = f_ * cs[p] + i_ * gg;
            float hn = o_ * tanhf(cn);
            cs[p] = cn;
            __half hr = __float2half(hn);
            nxth[b * Hdim + n0 + j] = hr;
            if (layer == 0) g_seq16[((size_t)t * 64 + b) * Hdim + n0 + j] = hr;
            if (t == Sq - 1) {
                g_h[layer][b * Hdim + n0 + j] = hn;
                g_c[layer][b * Hdim + n0 + j] = cn;
            }
        }
        __threadfence();
        __syncthreads();
        if (tid == 0) *(volatile unsigned*)&g_flag[cta * 8] = F0 + 2 + t;
    }
}

// ---------------- finalize: pack output tuple (seq_last, h_n[2], c_n[2]) ----------------
__global__ void finalize_kernel(float* __restrict__ out, int out_size) {
    int idx = blockIdx.x * 256 + threadIdx.x;  // 0..65535
    const int N1 = Bq * Hdim;
    if (idx + 0 * N1 < out_size) out[idx]          = g_h[1][idx];  // seq[:, -1, :]
    if (idx + 1 * N1 < out_size) out[idx + N1]     = g_h[0][idx];  // h_n layer 0
    if (idx + 2 * N1 < out_size) out[idx + 2 * N1] = g_h[1][idx];  // h_n layer 1
    if (idx + 3 * N1 < out_size) out[idx + 3 * N1] = g_c[0][idx];  // c_n layer 0
    if (idx + 4 * N1 < out_size) out[idx + 4 * N1] = g_c[1][idx];  // c_n layer 1
}

// ---------------- launch: 6 graph nodes total ----------------
extern "C" void kernel_launch(void* const* d_in, const int* in_sizes, int n_in,
                              void* d_out, int out_size) {
    const float* x  = (const float*)d_in[0];
    const float* Wi = (const float*)d_in[1];
    const float* bi = (const float*)d_in[2];
    const float* Wh = (const float*)d_in[3];
    const float* bh = (const float*)d_in[4];
    float* out = (float*)d_out;
    (void)in_sizes; (void)n_in;

    const int recur_smem = 81920 + 132096 + 8448 + 4096 + 2048;  // 228608 B
    cudaFuncSetAttribute(recur_kernel, cudaFuncAttributeMaxDynamicSharedMemorySize,
                         recur_smem);

    prep_kernel<<<131072, 256>>>(Wi, Wh, x);
    for (int l = 0; l < 2; l++) {
        proj_kernel<<<dim3(NG / 64, NROWS / 128), 256>>>(l, bi, bh);
        recur_kernel<<<NCTA, 512, recur_smem>>>(l);
    }
    finalize_kernel<<<256, 256>>>(out, out_size);
}